// round 7
// baseline (speedup 1.0000x reference)
#include <cuda_runtime.h>
#include <cuda_fp16.h>
#include <math.h>
#include <stdint.h>

#define E_EDGES 800000
#define NN      50000
#define BE      128
typedef unsigned long long ull;

__device__ int    g_idx64;
__device__ float  g_agg[(size_t)NN * 64];
__device__ float  g_P[(size_t)50048 * 512];   // [node][ P_src(256) | P_dst(256) ]
__device__ __half g_B1e[2 * 256 * 72];        // ef-part W1: [hi|lo][256 n][72 kpad]
__device__ __half g_BP[2 * 512 * 72];         // P-prep W1:  [hi|lo][512 n][72 kpad]
__device__ __half g_W2[2 * 2 * 64 * 136];     // [gate][hi|lo][64 n][136 kpad]
__device__ __half g_Wn1[2 * 128 * 136];       // node W1: [hi|lo][128 n][136 kpad]
__device__ __half g_Wn2[2 * 64 * 136];        // node W2: [hi|lo][64 n][136 kpad]

// ---------------- helpers ----------------------------------------------------
__device__ __forceinline__ uint32_t smem_u32(const void* p) {
    uint32_t a;
    asm("{ .reg .u64 t; cvta.to.shared.u64 t, %1; cvt.u32.u64 %0, t; }" : "=r"(a) : "l"(p));
    return a;
}
__device__ __forceinline__ void ldsm4(uint32_t* r, uint32_t addr) {
    asm volatile("ldmatrix.sync.aligned.m8n8.x4.shared.b16 {%0,%1,%2,%3}, [%4];"
                 : "=r"(r[0]), "=r"(r[1]), "=r"(r[2]), "=r"(r[3]) : "r"(addr));
}
__device__ __forceinline__ void mma16816(float* c, const uint32_t* a, uint32_t b0, uint32_t b1) {
    asm volatile("mma.sync.aligned.m16n8k16.row.col.f32.f16.f16.f32 "
                 "{%0,%1,%2,%3}, {%4,%5,%6,%7}, {%8,%9}, {%0,%1,%2,%3};"
                 : "+f"(c[0]), "+f"(c[1]), "+f"(c[2]), "+f"(c[3])
                 : "r"(a[0]), "r"(a[1]), "r"(a[2]), "r"(a[3]), "r"(b0), "r"(b1));
}
// f16-accumulate variant for split-correction terms (small magnitudes)
__device__ __forceinline__ void mma16816h(uint32_t* c, const uint32_t* a, uint32_t b0, uint32_t b1) {
    asm volatile("mma.sync.aligned.m16n8k16.row.col.f16.f16.f16.f16 "
                 "{%0,%1}, {%2,%3,%4,%5}, {%6,%7}, {%0,%1};"
                 : "+r"(c[0]), "+r"(c[1])
                 : "r"(a[0]), "r"(a[1]), "r"(a[2]), "r"(a[3]), "r"(b0), "r"(b1));
}
__device__ __forceinline__ void cpa16(uint32_t dst, const void* src) {
    asm volatile("cp.async.cg.shared.global [%0], [%1], 16;" :: "r"(dst), "l"(src));
}
#define CP_COMMIT() asm volatile("cp.async.commit_group;" ::: "memory")
#define CP_WAIT0()  asm volatile("cp.async.wait_group 0;" ::: "memory")
__device__ __forceinline__ void red2(float* p, float x, float y) {
    asm volatile("red.global.add.v2.f32 [%0], {%1,%2};" :: "l"(p), "f"(x), "f"(y) : "memory");
}
__device__ __forceinline__ uint32_t packh2(float x, float y) {
    __half2 h = __floats2half2_rn(x, y);
    return *(uint32_t*)&h;
}
__device__ __forceinline__ float2 unpackh2(uint32_t u) {
    return __half22float2(*(__half2*)&u);
}

// ---------------------------------------------------------------------------
// zp: zero g_agg (blocks 0..3124) + idx dtype detect (block 3125)
// ---------------------------------------------------------------------------
__global__ void zp_kernel(const unsigned int* __restrict__ raw) {
    if (blockIdx.x < 3125) {
        int i = blockIdx.x * 256 + threadIdx.x;
        ((float4*)g_agg)[i] = make_float4(0.f, 0.f, 0.f, 0.f);
    } else {
        __shared__ int any;
        if (threadIdx.x == 0) any = 0;
        __syncthreads();
        int f = 0;
        for (int i = threadIdx.x; i < 2048; i += blockDim.x)
            if (raw[2 * i + 1] != 0u) f = 1;
        if (f) atomicExch(&any, 1);
        __syncthreads();
        if (threadIdx.x == 0) g_idx64 = (any == 0) ? 1 : 0;
    }
}
// prepA: b1e (blocks 0..127) + w2 (blocks 128..255)
__global__ void prepA_kernel(const float* __restrict__ We1, const float* __restrict__ Wa1,
                             const float* __restrict__ We2, const float* __restrict__ Wa2) {
    if (blockIdx.x < 128) {
        int gi = blockIdx.x * 256 + threadIdx.x;    // 32768
        int p = gi >> 14, r = gi & 16383;
        int n = r >> 6, kk = r & 63;
        int k = 128 + kk;
        float w = (n < 128) ? We1[k * 128 + n] : Wa1[k * 128 + (n - 128)];
        __half hi = __float2half_rn(w);
        __half v = (p == 0) ? hi : __float2half_rn(w - __half2float(hi));
        g_B1e[(p * 256 + n) * 72 + kk] = v;
    } else {
        int gi = (blockIdx.x - 128) * 256 + threadIdx.x;  // 32768
        int g = gi >> 14, p = (gi >> 13) & 1;
        int r = gi & 8191, n = r >> 7, k = r & 127;
        const float* W = g ? Wa2 : We2;
        float w = W[k * 64 + n];
        __half hi = __float2half_rn(w);
        __half v = (p == 0) ? hi : __float2half_rn(w - __half2float(hi));
        g_W2[((g * 2 + p) * 64 + n) * 136 + k] = v;
    }
}
// prepB: bp (256 blocks)
__global__ void prepB_kernel(const float* __restrict__ We1, const float* __restrict__ Wa1) {
    int gi = blockIdx.x * 256 + threadIdx.x;        // 65536
    int p = gi >> 15, r = gi & 32767;
    int nIdx = r >> 6, kk = r & 63;
    int part = nIdx >> 8, c = nIdx & 255;
    int k = part * 64 + kk;
    float w = (c < 128) ? We1[k * 128 + c] : Wa1[k * 128 + (c - 128)];
    __half hi = __float2half_rn(w);
    __half v = (p == 0) ? hi : __float2half_rn(w - __half2float(hi));
    g_BP[(p * 512 + nIdx) * 72 + kk] = v;
}
// prepC: wn1 (blocks 0..127) + wn2 (blocks 128..191)
__global__ void prepC_kernel(const float* __restrict__ Wn1, const float* __restrict__ Wn2) {
    if (blockIdx.x < 128) {
        int gi = blockIdx.x * 256 + threadIdx.x;    // 32768
        int p = gi >> 14, r = gi & 16383;
        int n = r >> 7, k = r & 127;
        float w = Wn1[k * 128 + n];
        __half hi = __float2half_rn(w);
        __half v = (p == 0) ? hi : __float2half_rn(w - __half2float(hi));
        g_Wn1[(p * 128 + n) * 136 + k] = v;
    } else {
        int gi = (blockIdx.x - 128) * 256 + threadIdx.x;  // 16384
        int p = gi >> 13, r = gi & 8191;
        int n = r >> 7, k = r & 127;
        float w = Wn2[k * 64 + n];
        __half hi = __float2half_rn(w);
        __half v = (p == 0) ? hi : __float2half_rn(w - __half2float(hi));
        g_Wn2[(p * 64 + n) * 136 + k] = v;
    }
}

// ---------------------------------------------------------------------------
// prep_P: P[n][512] = nf[n] @ [W_src | W_dst], split-fp16 3-term HMMA.
// ---------------------------------------------------------------------------
#define PREP_SMEM 184320
__global__ __launch_bounds__(256, 1) void prep_P_kernel(const float* __restrict__ nf)
{
    extern __shared__ char smc[];
    const uint32_t smb = smem_u32(smc);
    const int tid = threadIdx.x, wid = tid >> 5, lane = tid & 31;
    const int m0 = blockIdx.x * 128;

    #pragma unroll
    for (int i = 0; i < 36; i++)
        cpa16(smb + 36864 + (tid + 256 * i) * 16, (const char*)g_BP + (tid + 256 * i) * 16);
    CP_COMMIT();

    {
        const int m = tid >> 1, h = tid & 1;
        const int node = m0 + m;
        const float* row = nf + (size_t)node * 64;
        #pragma unroll
        for (int it = 0; it < 8; it++) {
            int q = h * 8 + it;
            float4 v = (node < NN) ? ((const float4*)row)[q] : make_float4(0.f, 0.f, 0.f, 0.f);
            uint32_t h0 = packh2(v.x, v.y), h1 = packh2(v.z, v.w);
            float2 f0 = unpackh2(h0), f1 = unpackh2(h1);
            uint32_t l0 = packh2(v.x - f0.x, v.y - f0.y), l1 = packh2(v.z - f1.x, v.w - f1.y);
            *(uint2*)(smc + 0     + m * 144 + q * 8) = make_uint2(h0, h1);
            *(uint2*)(smc + 18432 + m * 144 + q * 8) = make_uint2(l0, l1);
        }
    }
    CP_WAIT0();
    __syncthreads();

    const int wr = wid * 16;
    const uint32_t aH = smb + (uint32_t)((wr + (lane & 15)) * 144 + ((lane >> 4) * 8) * 2);
    const uint32_t aL = aH + 18432;
    const uint32_t bln = (uint32_t)((((lane >> 4) << 3) + (lane & 7)) * 144 + (((lane >> 3) & 1) ? 16 : 0));
    const int r0 = wr + (lane >> 2);
    const int ec = 2 * (lane & 3);

    #pragma unroll
    for (int p = 0; p < 2; p++) {
        float acc[128];
        #pragma unroll
        for (int i = 0; i < 128; i++) acc[i] = 0.f;
        const uint32_t bH = smb + 36864  + (uint32_t)(p * 36864) + bln;
        const uint32_t bL = bH + 73728;
        #pragma unroll
        for (int ks = 0; ks < 4; ks++) {
            uint32_t ah[4], al[4];
            ldsm4(ah, aH + ks * 32);
            ldsm4(al, aL + ks * 32);
            #pragma unroll
            for (int j2 = 0; j2 < 16; j2++) {
                uint32_t bh[4], bl[4];
                ldsm4(bh, bH + j2 * 2304 + ks * 32);
                ldsm4(bl, bL + j2 * 2304 + ks * 32);
                mma16816(&acc[(2*j2+0)*4], ah, bh[0], bh[1]); mma16816(&acc[(2*j2+1)*4], ah, bh[2], bh[3]);
                mma16816(&acc[(2*j2+0)*4], al, bh[0], bh[1]); mma16816(&acc[(2*j2+1)*4], al, bh[2], bh[3]);
                mma16816(&acc[(2*j2+0)*4], ah, bl[0], bl[1]); mma16816(&acc[(2*j2+1)*4], ah, bl[2], bl[3]);
            }
        }
        #pragma unroll
        for (int j8 = 0; j8 < 32; j8++) {
            int cb = p * 256 + 8 * j8 + ec;
            *(float2*)(g_P + (size_t)(m0 + r0) * 512 + cb)     = make_float2(acc[4*j8+0], acc[4*j8+1]);
            *(float2*)(g_P + (size_t)(m0 + r0 + 8) * 512 + cb) = make_float2(acc[4*j8+2], acc[4*j8+3]);
        }
    }
}

// ---------------------------------------------------------------------------
// Edge kernel SMEM map (bytes): same as R6
// ---------------------------------------------------------------------------
#define OFF_A1H  0
#define OFF_A1L  18432
#define OFF_B1   36864
#define OFF_PS   73728
#define OFF_W2   0
#define OFF_MISC 206848
#define EDGE_SMEM 209408
#define PSTR 260

__global__ __launch_bounds__(256, 1) void edge_kernel(
    const float* __restrict__ ef,
    const int* __restrict__ rawsrc, const int* __restrict__ rawdst,
    const float* __restrict__ be1, const float* __restrict__ ba1,
    const float* __restrict__ be2, const float* __restrict__ ba2,
    float* __restrict__ ef_out)
{
    extern __shared__ char smc[];
    const uint32_t smb = smem_u32(smc);
    const int tid = threadIdx.x, wid = tid >> 5, lane = tid & 31;
    const int e0 = blockIdx.x * BE;

    int*   sSrc  = (int*)(smc + OFF_MISC);
    int*   sDst  = (int*)(smc + OFF_MISC + 512);
    float* sBias = (float*)(smc + OFF_MISC + 1024);
    float* sB2b  = (float*)(smc + OFF_MISC + 2048);
    float* sPs   = (float*)(smc + OFF_PS);

    const int is64 = g_idx64;
    if (tid < BE) sSrc[tid] = is64 ? rawsrc[2 * (e0 + tid)] : rawsrc[e0 + tid];
    else { int m = tid - BE; sDst[m] = is64 ? rawdst[2 * (e0 + m)] : rawdst[e0 + m]; }

    if (tid < 64)
        ((float4*)sBias)[tid] = (tid < 32) ? ((const float4*)be1)[tid] : ((const float4*)ba1)[tid - 32];
    else if (tid < 96)
        ((float4*)sB2b)[tid - 64] = (tid < 80) ? ((const float4*)be2)[tid - 64] : ((const float4*)ba2)[tid - 80];

    // stage B1-hi
    #pragma unroll
    for (int i = 0; i < 9; i++)
        cpa16(smb + OFF_B1 + (tid + 256 * i) * 16, (const char*)g_B1e + (tid + 256 * i) * 16);
    CP_COMMIT();

    // gather ef rows, split hi/lo
    {
        const int m = tid >> 1, h = tid & 1;
        const float* row = ef + (size_t)(e0 + m) * 64;
        #pragma unroll
        for (int it = 0; it < 8; it++) {
            int q = h * 8 + it;
            float4 v = ((const float4*)row)[q];
            uint32_t h0 = packh2(v.x, v.y), h1 = packh2(v.z, v.w);
            float2 f0 = unpackh2(h0), f1 = unpackh2(h1);
            uint32_t l0 = packh2(v.x - f0.x, v.y - f0.y), l1 = packh2(v.z - f1.x, v.w - f1.y);
            *(uint2*)(smc + OFF_A1H + m * 144 + q * 8) = make_uint2(h0, h1);
            *(uint2*)(smc + OFF_A1L + m * 144 + q * 8) = make_uint2(l0, l1);
        }
    }
    CP_WAIT0();
    __syncthreads();

    const int wr = wid * 16;
    const uint32_t aH = smb + OFF_A1H + (uint32_t)((wr + (lane & 15)) * 144 + ((lane >> 4) * 8) * 2);
    const uint32_t aL = aH + 18432;
    const uint32_t bln = (uint32_t)((((lane >> 4) << 3) + (lane & 7)) * 144 + (((lane >> 3) & 1) ? 16 : 0));
    const uint32_t bB = smb + OFF_B1 + bln;

    float acc[128];
    uint32_t accL[64];
    #pragma unroll
    for (int i = 0; i < 128; i++) acc[i] = 0.f;
    #pragma unroll
    for (int i = 0; i < 64; i++) accL[i] = 0u;

    // ---- GEMM1 pass1: xh@Wh (f32 acc) + xl@Wh (f16 acc), interleaved P gather ----
    #pragma unroll
    for (int ks = 0; ks < 4; ks++) {
        #pragma unroll
        for (int t = 0; t < 2; t++) {
            int m = (wid << 4) + ks * 2 + t;
            const float4* ps = (const float4*)(g_P + (size_t)sSrc[m] * 512);
            const float4* pd = (const float4*)(g_P + (size_t)sDst[m] * 512 + 256);
            #pragma unroll
            for (int j = 0; j < 2; j++) {
                int f4 = lane + 32 * j;
                float4 a = ps[f4], b = pd[f4];
                *(float4*)(sPs + m * PSTR + f4 * 4) =
                    make_float4(a.x + b.x, a.y + b.y, a.z + b.z, a.w + b.w);
            }
        }
        uint32_t ah[4], al[4];
        ldsm4(ah, aH + ks * 32);
        ldsm4(al, aL + ks * 32);
        #pragma unroll
        for (int j2 = 0; j2 < 16; j2++) {
            uint32_t bh[4];
            ldsm4(bh, bB + j2 * 2304 + ks * 32);
            mma16816(&acc[(2*j2+0)*4], ah, bh[0], bh[1]);
            mma16816(&acc[(2*j2+1)*4], ah, bh[2], bh[3]);
            mma16816h(&accL[(2*j2+0)*2], al, bh[0], bh[1]);
            mma16816h(&accL[(2*j2+1)*2], al, bh[2], bh[3]);
        }
    }
    __syncthreads();   // pass1 B reads done

    // reload B1 with W-lo; overlap with remaining P gather
    #pragma unroll
    for (int i = 0; i < 9; i++)
        cpa16(smb + OFF_B1 + (tid + 256 * i) * 16, (const char*)g_B1e + 36864 + (tid + 256 * i) * 16);
    CP_COMMIT();
    #pragma unroll
    for (int it = 8; it < 16; it++) {
        int m = (wid << 4) + it;
        const float4* ps = (const float4*)(g_P + (size_t)sSrc[m] * 512);
        const float4* pd = (const float4*)(g_P + (size_t)sDst[m] * 512 + 256);
        #pragma unroll
        for (int j = 0; j < 2; j++) {
            int f4 = lane + 32 * j;
            float4 a = ps[f4], b = pd[f4];
            *(float4*)(sPs + m * PSTR + f4 * 4) =
                make_float4(a.x + b.x, a.y + b.y, a.z + b.z, a.w + b.w);
        }
    }
    CP_WAIT0();
    __syncthreads();

    // ---- GEMM1 pass2: xh@Wl (f16 acc) ----
    #pragma unroll
    for (int ks = 0; ks < 4; ks++) {
        uint32_t ah[4];
        ldsm4(ah, aH + ks * 32);
        #pragma unroll
        for (int j2 = 0; j2 < 16; j2++) {
            uint32_t bl[4];
            ldsm4(bl, bB + j2 * 2304 + ks * 32);
            mma16816h(&accL[(2*j2+0)*2], ah, bl[0], bl[1]);
            mma16816h(&accL[(2*j2+1)*2], ah, bl[2], bl[3]);
        }
    }
    __syncthreads();   // A1/B1 dead

    // merge f16 corrections into f32 acc
    #pragma unroll
    for (int t = 0; t < 32; t++) {
        float2 u = unpackh2(accL[2*t]);
        float2 v = unpackh2(accL[2*t+1]);
        acc[4*t+0] += u.x; acc[4*t+1] += u.y;
        acc[4*t+2] += v.x; acc[4*t+3] += v.y;
    }

    // stage W2 into @0 (overlapped with epilogue 1)
    #pragma unroll
    for (int i = 0; i < 17; i++)
        cpa16(smb + OFF_W2 + (tid + 256 * i) * 16, (const char*)g_W2 + (tid + 256 * i) * 16);
    CP_COMMIT();

    // ---- epilogue 1: H = relu(acc + Psum + bias) -> hi/lo h2 regs ----
    uint32_t hH[64], hL[64];
    {
        const int r0 = wr + (lane >> 2);
        const int ec = 2 * (lane & 3);
        #pragma unroll
        for (int j8 = 0; j8 < 32; j8++) {
            int cb = 8 * j8 + ec;
            float2 p0 = *(float2*)(sPs + r0 * PSTR + cb);
            float2 p1 = *(float2*)(sPs + (r0 + 8) * PSTR + cb);
            float b0 = sBias[cb], b1 = sBias[cb + 1];
            float v0 = fmaxf(acc[4*j8+0] + p0.x + b0, 0.f);
            float v1 = fmaxf(acc[4*j8+1] + p0.y + b1, 0.f);
            float v2 = fmaxf(acc[4*j8+2] + p1.x + b0, 0.f);
            float v3 = fmaxf(acc[4*j8+3] + p1.y + b1, 0.f);
            uint32_t h01 = packh2(v0, v1);
            float2 f01 = unpackh2(h01);
            uint32_t l01 = packh2(v0 - f01.x, v1 - f01.y);
            uint32_t h23 = packh2(v2, v3);
            float2 f23 = unpackh2(h23);
            uint32_t l23 = packh2(v2 - f23.x, v3 - f23.y);
            hH[2*j8]   = h01; hL[2*j8]   = l01;
            hH[2*j8+1] = h23; hL[2*j8+1] = l23;
        }
    }
    CP_WAIT0();
    __syncthreads();

    // ---- GEMM2: Hh@W2h (f32 acc) + corrections (f16 acc) ----
    const uint32_t w2ln = (uint32_t)((((lane >> 4) << 3) + (lane & 7)) * 272 + (((lane >> 3) & 1) ? 16 : 0));
    float acc2[64];
    uint32_t acc2l[32];
    #pragma unroll
    for (int i = 0; i < 64; i++) acc2[i] = 0.f;
    #pragma unroll
    for (int i = 0; i < 32; i++) acc2l[i] = 0u;

    #pragma unroll
    for (int hf = 0; hf < 2; hf++) {
        const uint32_t wb = smb + OFF_W2 + (uint32_t)(hf * 34816) + w2ln;
        #pragma unroll
        for (int kc = 0; kc < 8; kc++) {
            int jb = 2 * (hf * 16 + 2 * kc);
            uint32_t ah[4] = { hH[jb], hH[jb+1], hH[jb+2], hH[jb+3] };
            uint32_t al[4] = { hL[jb], hL[jb+1], hL[jb+2], hL[jb+3] };
            #pragma unroll
            for (int j2 = 0; j2 < 4; j2++) {
                uint32_t bh[4], bl[4];
                ldsm4(bh, wb + j2 * 4352 + kc * 32);
                ldsm4(bl, wb + 17408 + j2 * 4352 + kc * 32);
                float*    c0 = &acc2[hf * 32 + (2*j2+0) * 4];
                float*    c1 = &acc2[hf * 32 + (2*j2+1) * 4];
                uint32_t* l0 = &acc2l[hf * 16 + (2*j2+0) * 2];
                uint32_t* l1 = &acc2l[hf * 16 + (2*j2+1) * 2];
                mma16816(c0, ah, bh[0], bh[1]);  mma16816(c1, ah, bh[2], bh[3]);
                mma16816h(l0, al, bh[0], bh[1]); mma16816h(l1, al, bh[2], bh[3]);
                mma16816h(l0, ah, bl[0], bl[1]); mma16816h(l1, ah, bl[2], bl[3]);
            }
        }
    }

    // ---- epilogue 2 ----
    {
        const int r0 = wr + (lane >> 2), r1 = r0 + 8;
        const int ec = 2 * (lane & 3);
        const int d0 = sDst[r0], d1 = sDst[r1];
        float* eo0 = ef_out + (size_t)(e0 + r0) * 64;
        float* eo1 = ef_out + (size_t)(e0 + r1) * 64;
        float* ag0 = g_agg + (size_t)d0 * 64;
        float* ag1 = g_agg + (size_t)d1 * 64;
        #pragma unroll
        for (int j8 = 0; j8 < 8; j8++) {
            int cb = j8 * 8 + ec;
            float be0 = sB2b[cb], be1v = sB2b[cb + 1];
            float ba0 = sB2b[64 + cb], ba1v = sB2b[64 + cb + 1];
            float2 le0 = unpackh2(acc2l[j8*2]);        // e-gate, rows r0
            float2 le1 = unpackh2(acc2l[j8*2+1]);      // e-gate, rows r1
            float2 la0 = unpackh2(acc2l[16 + j8*2]);   // a-gate, rows r0
            float2 la1 = unpackh2(acc2l[16 + j8*2+1]); // a-gate, rows r1
            float ex0 = acc2[j8*4+0] + le0.x + be0, ex1 = acc2[j8*4+1] + le0.y + be1v;
            float ax0 = acc2[32 + j8*4+0] + la0.x + ba0, ax1 = acc2[32 + j8*4+1] + la0.y + ba1v;
            float m0 = ex0 / (1.f + __expf(-ax0));
            float m1 = ex1 / (1.f + __expf(-ax1));
            *(float2*)(eo0 + cb) = make_float2(m0, m1);
            red2(ag0 + cb, m0, m1);
            float ey0 = acc2[j8*4+2] + le1.x + be0, ey1 = acc2[j8*4+3] + le1.y + be1v;
            float ay0 = acc2[32 + j8*4+2] + la1.x + ba0, ay1 = acc2[32 + j8*4+3] + la1.y + ba1v;
            float n0 = ey0 / (1.f + __expf(-ay0));
            float n1 = ey1 / (1.f + __expf(-ay1));
            *(float2*)(eo1 + cb) = make_float2(n0, n1);
            red2(ag1 + cb, n0, n1);
        }
    }
}

// ---------------------------------------------------------------------------
// Node kernel (HMMA, f16-acc corrections)
// ---------------------------------------------------------------------------
#define NOFF_B1  69632
#define NOFF_W2  139264
#define NOFF_MSC 174080
#define NODE_SMEM 174848

__global__ __launch_bounds__(256, 1) void node_kernel(
    const float* __restrict__ nf,
    const float* __restrict__ bn1, const float* __restrict__ bn2,
    float* __restrict__ nf_out)
{
    extern __shared__ char smc[];
    const uint32_t smb = smem_u32(smc);
    const int tid = threadIdx.x, wid = tid >> 5, lane = tid & 31;
    const int m0 = blockIdx.x * 128;
    float* sB1b = (float*)(smc + NOFF_MSC);
    float* sB2b = (float*)(smc + NOFF_MSC + 512);

    #pragma unroll
    for (int i = 0; i < 17; i++)
        cpa16(smb + NOFF_B1 + (tid + 256 * i) * 16, (const char*)g_Wn1 + (tid + 256 * i) * 16);
    #pragma unroll
    for (int i = 0; i < 9; i++) {
        int idx = tid + 256 * i;
        if (idx < 2176) cpa16(smb + NOFF_W2 + idx * 16, (const char*)g_Wn2 + idx * 16);
    }
    CP_COMMIT();

    if (tid < 32) ((float4*)sB1b)[tid] = ((const float4*)bn1)[tid];
    else if (tid < 48) ((float4*)sB2b)[tid - 32] = ((const float4*)bn2)[tid - 32];

    {
        const int m = tid >> 1, h = tid & 1;
        const int node = m0 + m;
        const float4* src = (h == 0) ? (const float4*)(g_agg + (size_t)node * 64)
                                     : (const float4*)(nf + (size_t)node * 64);
        #pragma unroll
        for (int it = 0; it < 16; it++) {
            float4 v = (node < NN) ? src[it] : make_float4(0.f, 0.f, 0.f, 0.f);
            int k = h * 64 + it * 4;
            uint32_t h0 = packh2(v.x, v.y), h1 = packh2(v.z, v.w);
            float2 f0 = unpackh2(h0), f1 = unpackh2(h1);
            uint32_t l0 = packh2(v.x - f0.x, v.y - f0.y), l1 = packh2(v.z - f1.x, v.w - f1.y);
            *(uint2*)(smc + 0     + m * 272 + k * 2) = make_uint2(h0, h1);
            *(uint2*)(smc + 34816 + m * 272 + k * 2) = make_uint2(l0, l1);
        }
    }
    CP_WAIT0();
    __syncthreads();

    const int wr = wid * 16;
    const uint32_t aH = smb + (uint32_t)((wr + (lane & 15)) * 272 + ((lane >> 4) * 8) * 2);
    const uint32_t aL = aH + 34816;
    const uint32_t bln = (uint32_t)((((lane >> 4) << 3) + (lane & 7)) * 272 + (((lane >> 3) & 1) ? 16 : 0));

    float acc[64];
    uint32_t accL[32];
    #pragma unroll
    for (int i = 0; i < 64; i++) acc[i] = 0.f;
    #pragma unroll
    for (int i = 0; i < 32; i++) accL[i] = 0u;
    {
        const uint32_t bH = smb + NOFF_B1 + bln;
        const uint32_t bL = bH + 34816;
        #pragma unroll
        for (int ks = 0; ks < 8; ks++) {
            uint32_t ah[4], al[4];
            ldsm4(ah, aH + ks * 32);
            ldsm4(al, aL + ks * 32);
            #pragma unroll
            for (int j2 = 0; j2 < 8; j2++) {
                uint32_t bh[4], bl[4];
                ldsm4(bh, bH + j2 * 4352 + ks * 32);
                ldsm4(bl, bL + j2 * 4352 + ks * 32);
                float*    c0 = &acc[(2*j2+0)*4];
                float*    c1 = &acc[(2*j2+1)*4];
                uint32_t* l0 = &accL[(2*j2+0)*2];
                uint32_t* l1 = &accL[(2*j2+1)*2];
                mma16816(c0, ah, bh[0], bh[1]);  mma16816(c1, ah, bh[2], bh[3]);
                mma16816h(l0, al, bh[0], bh[1]); mma16816h(l1, al, bh[2], bh[3]);
                mma16816h(l0, ah, bl[0], bl[1]); mma16816h(l1, ah, bl[2], bl[3]);
            }
        }
    }
    #pragma unroll
    for (int t = 0; t < 16; t++) {
        float2 u = unpackh2(accL[2*t]);
        float2 v = unpackh2(accL[2*t+1]);
        acc[4*t+0] += u.x; acc[4*t+1] += u.y;
        acc[4*t+2] += v.x; acc[4*t+3] += v.y;
    }

    uint32_t hH[32], hL[32];
    {
        const int ec = 2 * (lane & 3);
        #pragma unroll
        for (int j8 = 0; j8 < 16; j8++) {
            int cb = 8 * j8 + ec;
            float b0 = sB1b[cb], b1 = sB1b[cb + 1];
            float v0 = fmaxf(acc[4*j8+0] + b0, 0.f);
            float v1 = fmaxf(acc[4*j8+1] + b1, 0.f);
            float v2 = fmaxf(acc[4*j8+2] + b0, 0.f);
            float v3 = fmaxf(acc[4*j8+3] + b1, 0.f);
            uint32_t h01 = packh2(v0, v1);
            float2 f01 = unpackh2(h01);
            uint32_t l01 = packh2(v0 - f01.x, v1 - f01.y);
            uint32_t h23 = packh2(v2, v3);
            float2 f23 = unpackh2(h23);
            uint32_t l23 = packh2(v2 - f23.x, v3 - f23.y);
            hH[2*j8] = h01; hL[2*j8] = l01;
            hH[2*j8+1] = h23; hL[2*j8+1] = l23;
        }
    }

    float acc2[32];
    uint32_t acc2l[16];
    #pragma unroll
    for (int i = 0; i < 32; i++) acc2[i] = 0.f;
    #pragma unroll
    for (int i = 0; i < 16; i++) acc2l[i] = 0u;
    {
        const uint32_t wb = smb + NOFF_W2 + bln;
        #pragma unroll
        for (int kc = 0; kc < 8; kc++) {
            uint32_t ah[4] = { hH[4*kc], hH[4*kc+1], hH[4*kc+2], hH[4*kc+3] };
            uint32_t al[4] = { hL[4*kc], hL[4*kc+1], hL[4*kc+2], hL[4*kc+3] };
            #pragma unroll
            for (int j2 = 0; j2 < 4; j2++) {
                uint32_t bh[4], bl[4];
                ldsm4(bh, wb + j2 * 4352 + kc * 32);
                ldsm4(bl, wb + 17408 + j2 * 4352 + kc * 32);
                float*    c0 = &acc2[(2*j2+0)*4];
                float*    c1 = &acc2[(2*j2+1)*4];
                uint32_t* l0 = &acc2l[(2*j2+0)*2];
                uint32_t* l1 = &acc2l[(2*j2+1)*2];
                mma16816(c0, ah, bh[0], bh[1]);  mma16816(c1, ah, bh[2], bh[3]);
                mma16816h(l0, al, bh[0], bh[1]); mma16816h(l1, al, bh[2], bh[3]);
                mma16816h(l0, ah, bl[0], bl[1]); mma16816h(l1, ah, bl[2], bl[3]);
            }
        }
    }

    {
        const int r0 = wr + (lane >> 2);
        const int ec = 2 * (lane & 3);
        const int n0 = m0 + r0, n1 = n0 + 8;
        #pragma unroll
        for (int j8 = 0; j8 < 8; j8++) {
            int cb = 8 * j8 + ec;
            float b0 = sB2b[cb], b1 = sB2b[cb + 1];
            float2 u = unpackh2(acc2l[2*j8]);
            float2 v = unpackh2(acc2l[2*j8+1]);
            if (n0 < NN)
                *(float2*)(nf_out + (size_t)n0 * 64 + cb) =
                    make_float2(acc2[4*j8+0] + u.x + b0, acc2[4*j8+1] + u.y + b1);
            if (n1 < NN)
                *(float2*)(nf_out + (size_t)n1 * 64 + cb) =
                    make_float2(acc2[4*j8+2] + v.x + b0, acc2[4*j8+3] + v.y + b1);
        }
    }
}

// ---------------------------------------------------------------------------
extern "C" void kernel_launch(void* const* d_in, const int* in_sizes, int n_in,
                              void* d_out, int out_size)
{
    const float* nf  = (const float*)d_in[0];
    const float* ef  = (const float*)d_in[1];
    const float* We1 = (const float*)d_in[4];
    const float* be1 = (const float*)d_in[5];
    const float* We2 = (const float*)d_in[6];
    const float* be2 = (const float*)d_in[7];
    const float* Wa1 = (const float*)d_in[8];
    const float* ba1 = (const float*)d_in[9];
    const float* Wa2 = (const float*)d_in[10];
    const float* ba2 = (const float*)d_in[11];
    const float* Wn1 = (const float*)d_in[12];
    const float* bn1 = (const float*)d_in[13];
    const float* Wn2 = (const float*)d_in[14];
    const float* bn2 = (const float*)d_in[15];

    float* nf_out = (float*)d_out;
    float* ef_out = nf_out + (size_t)NN * 64;

    cudaFuncSetAttribute(prep_P_kernel, cudaFuncAttributeMaxDynamicSharedMemorySize, PREP_SMEM);
    cudaFuncSetAttribute(edge_kernel, cudaFuncAttributeMaxDynamicSharedMemorySize, EDGE_SMEM);
    cudaFuncSetAttribute(node_kernel, cudaFuncAttributeMaxDynamicSharedMemorySize, NODE_SMEM);

    // launch order chosen so ncu (-s 5 -c 1) captures edge_kernel (6th launch)
    zp_kernel<<<3126, 256>>>((const unsigned int*)d_in[2]);   // 1
    prepA_kernel<<<256, 256>>>(We1, Wa1, We2, Wa2);           // 2
    prepB_kernel<<<256, 256>>>(We1, Wa1);                     // 3
    prepC_kernel<<<192, 256>>>(Wn1, Wn2);                     // 4
    prep_P_kernel<<<391, 256, PREP_SMEM>>>(nf);               // 5
    edge_kernel<<<E_EDGES / BE, 256, EDGE_SMEM>>>(            // 6 <- ncu lands here
        ef, (const int*)d_in[2], (const int*)d_in[3],
        be1, ba1, be2, ba2, ef_out);
    node_kernel<<<391, 256, NODE_SMEM>>>(nf, bn1, bn2, nf_out); // 7
}

// round 8
// speedup vs baseline: 1.0562x; 1.0562x over previous
#include <cuda_runtime.h>
#include <cuda_fp16.h>
#include <math.h>
#include <stdint.h>

#define E_EDGES 800000
#define NN      50000
typedef unsigned long long ull;

__device__ int    g_idx64;
__device__ float  g_agg[(size_t)NN * 64];
__device__ float  g_P[(size_t)50048 * 512];   // [node][ P_src(256) | P_dst(256) ]
__device__ __half g_B1e[2 * 256 * 72];        // ef-part W1: [hi|lo][256 n][72 kpad]
__device__ __half g_BP[2 * 512 * 72];         // P-prep W1:  [hi|lo][512 n][72 kpad]
__device__ __half g_W2[2 * 2 * 64 * 136];     // [gate][hi|lo][64 n][136 kpad]
__device__ __half g_Wn1[2 * 128 * 136];       // node W1: [hi|lo][128 n][136 kpad]
__device__ __half g_Wn2[2 * 64 * 136];        // node W2: [hi|lo][64 n][136 kpad]

// ---------------- helpers ----------------------------------------------------
__device__ __forceinline__ uint32_t smem_u32(const void* p) {
    uint32_t a;
    asm("{ .reg .u64 t; cvta.to.shared.u64 t, %1; cvt.u32.u64 %0, t; }" : "=r"(a) : "l"(p));
    return a;
}
__device__ __forceinline__ void ldsm4(uint32_t* r, uint32_t addr) {
    asm volatile("ldmatrix.sync.aligned.m8n8.x4.shared.b16 {%0,%1,%2,%3}, [%4];"
                 : "=r"(r[0]), "=r"(r[1]), "=r"(r[2]), "=r"(r[3]) : "r"(addr));
}
__device__ __forceinline__ void mma16816(float* c, const uint32_t* a, uint32_t b0, uint32_t b1) {
    asm volatile("mma.sync.aligned.m16n8k16.row.col.f32.f16.f16.f32 "
                 "{%0,%1,%2,%3}, {%4,%5,%6,%7}, {%8,%9}, {%0,%1,%2,%3};"
                 : "+f"(c[0]), "+f"(c[1]), "+f"(c[2]), "+f"(c[3])
                 : "r"(a[0]), "r"(a[1]), "r"(a[2]), "r"(a[3]), "r"(b0), "r"(b1));
}
__device__ __forceinline__ void cpa16(uint32_t dst, const void* src) {
    asm volatile("cp.async.cg.shared.global [%0], [%1], 16;" :: "r"(dst), "l"(src));
}
#define CP_COMMIT() asm volatile("cp.async.commit_group;" ::: "memory")
#define CP_WAIT0()  asm volatile("cp.async.wait_group 0;" ::: "memory")
#define CP_WAIT1()  asm volatile("cp.async.wait_group 1;" ::: "memory")
__device__ __forceinline__ void red2(float* p, float x, float y) {
    asm volatile("red.global.add.v2.f32 [%0], {%1,%2};" :: "l"(p), "f"(x), "f"(y) : "memory");
}
__device__ __forceinline__ uint32_t packh2(float x, float y) {
    __half2 h = __floats2half2_rn(x, y);
    return *(uint32_t*)&h;
}
__device__ __forceinline__ float2 unpackh2(uint32_t u) {
    return __half22float2(*(__half2*)&u);
}

// ---------------------------------------------------------------------------
__global__ void zp_kernel(const unsigned int* __restrict__ raw) {
    if (blockIdx.x < 3125) {
        int i = blockIdx.x * 256 + threadIdx.x;
        ((float4*)g_agg)[i] = make_float4(0.f, 0.f, 0.f, 0.f);
    } else {
        __shared__ int any;
        if (threadIdx.x == 0) any = 0;
        __syncthreads();
        int f = 0;
        for (int i = threadIdx.x; i < 2048; i += blockDim.x)
            if (raw[2 * i + 1] != 0u) f = 1;
        if (f) atomicExch(&any, 1);
        __syncthreads();
        if (threadIdx.x == 0) g_idx64 = (any == 0) ? 1 : 0;
    }
}
__global__ void prepA_kernel(const float* __restrict__ We1, const float* __restrict__ Wa1,
                             const float* __restrict__ We2, const float* __restrict__ Wa2) {
    if (blockIdx.x < 128) {
        int gi = blockIdx.x * 256 + threadIdx.x;
        int p = gi >> 14, r = gi & 16383;
        int n = r >> 6, kk = r & 63;
        int k = 128 + kk;
        float w = (n < 128) ? We1[k * 128 + n] : Wa1[k * 128 + (n - 128)];
        __half hi = __float2half_rn(w);
        __half v = (p == 0) ? hi : __float2half_rn(w - __half2float(hi));
        g_B1e[(p * 256 + n) * 72 + kk] = v;
    } else {
        int gi = (blockIdx.x - 128) * 256 + threadIdx.x;
        int g = gi >> 14, p = (gi >> 13) & 1;
        int r = gi & 8191, n = r >> 7, k = r & 127;
        const float* W = g ? Wa2 : We2;
        float w = W[k * 64 + n];
        __half hi = __float2half_rn(w);
        __half v = (p == 0) ? hi : __float2half_rn(w - __half2float(hi));
        g_W2[((g * 2 + p) * 64 + n) * 136 + k] = v;
    }
}
__global__ void prepB_kernel(const float* __restrict__ We1, const float* __restrict__ Wa1) {
    int gi = blockIdx.x * 256 + threadIdx.x;
    int p = gi >> 15, r = gi & 32767;
    int nIdx = r >> 6, kk = r & 63;
    int part = nIdx >> 8, c = nIdx & 255;
    int k = part * 64 + kk;
    float w = (c < 128) ? We1[k * 128 + c] : Wa1[k * 128 + (c - 128)];
    __half hi = __float2half_rn(w);
    __half v = (p == 0) ? hi : __float2half_rn(w - __half2float(hi));
    g_BP[(p * 512 + nIdx) * 72 + kk] = v;
}
__global__ void prepC_kernel(const float* __restrict__ Wn1, const float* __restrict__ Wn2) {
    if (blockIdx.x < 128) {
        int gi = blockIdx.x * 256 + threadIdx.x;
        int p = gi >> 14, r = gi & 16383;
        int n = r >> 7, k = r & 127;
        float w = Wn1[k * 128 + n];
        __half hi = __float2half_rn(w);
        __half v = (p == 0) ? hi : __float2half_rn(w - __half2float(hi));
        g_Wn1[(p * 128 + n) * 136 + k] = v;
    } else {
        int gi = (blockIdx.x - 128) * 256 + threadIdx.x;
        int p = gi >> 13, r = gi & 8191;
        int n = r >> 7, k = r & 127;
        float w = Wn2[k * 64 + n];
        __half hi = __float2half_rn(w);
        __half v = (p == 0) ? hi : __float2half_rn(w - __half2float(hi));
        g_Wn2[(p * 64 + n) * 136 + k] = v;
    }
}

// ---------------------------------------------------------------------------
// prep_P: P[n][512] = nf[n] @ [W_src | W_dst], split-fp16 3-term HMMA.
// ---------------------------------------------------------------------------
#define PREP_SMEM 184320
__global__ __launch_bounds__(256, 1) void prep_P_kernel(const float* __restrict__ nf)
{
    extern __shared__ char smc[];
    const uint32_t smb = smem_u32(smc);
    const int tid = threadIdx.x, wid = tid >> 5, lane = tid & 31;
    const int m0 = blockIdx.x * 128;

    #pragma unroll
    for (int i = 0; i < 36; i++)
        cpa16(smb + 36864 + (tid + 256 * i) * 16, (const char*)g_BP + (tid + 256 * i) * 16);
    CP_COMMIT();

    {
        const int m = tid >> 1, h = tid & 1;
        const int node = m0 + m;
        const float* row = nf + (size_t)node * 64;
        #pragma unroll
        for (int it = 0; it < 8; it++) {
            int q = h * 8 + it;
            float4 v = (node < NN) ? ((const float4*)row)[q] : make_float4(0.f, 0.f, 0.f, 0.f);
            uint32_t h0 = packh2(v.x, v.y), h1 = packh2(v.z, v.w);
            float2 f0 = unpackh2(h0), f1 = unpackh2(h1);
            uint32_t l0 = packh2(v.x - f0.x, v.y - f0.y), l1 = packh2(v.z - f1.x, v.w - f1.y);
            *(uint2*)(smc + 0     + m * 144 + q * 8) = make_uint2(h0, h1);
            *(uint2*)(smc + 18432 + m * 144 + q * 8) = make_uint2(l0, l1);
        }
    }
    CP_WAIT0();
    __syncthreads();

    const int wr = wid * 16;
    const uint32_t aH = smb + (uint32_t)((wr + (lane & 15)) * 144 + ((lane >> 4) * 8) * 2);
    const uint32_t aL = aH + 18432;
    const uint32_t bln = (uint32_t)((((lane >> 4) << 3) + (lane & 7)) * 144 + (((lane >> 3) & 1) ? 16 : 0));
    const int r0 = wr + (lane >> 2);
    const int ec = 2 * (lane & 3);

    #pragma unroll
    for (int p = 0; p < 2; p++) {
        float acc[128];
        #pragma unroll
        for (int i = 0; i < 128; i++) acc[i] = 0.f;
        const uint32_t bH = smb + 36864  + (uint32_t)(p * 36864) + bln;
        const uint32_t bL = bH + 73728;
        #pragma unroll
        for (int ks = 0; ks < 4; ks++) {
            uint32_t ah[4], al[4];
            ldsm4(ah, aH + ks * 32);
            ldsm4(al, aL + ks * 32);
            #pragma unroll
            for (int j2 = 0; j2 < 16; j2++) {
                uint32_t bh[4], bl[4];
                ldsm4(bh, bH + j2 * 2304 + ks * 32);
                ldsm4(bl, bL + j2 * 2304 + ks * 32);
                mma16816(&acc[(2*j2+0)*4], ah, bh[0], bh[1]); mma16816(&acc[(2*j2+1)*4], ah, bh[2], bh[3]);
                mma16816(&acc[(2*j2+0)*4], al, bh[0], bh[1]); mma16816(&acc[(2*j2+1)*4], al, bh[2], bh[3]);
                mma16816(&acc[(2*j2+0)*4], ah, bl[0], bl[1]); mma16816(&acc[(2*j2+1)*4], ah, bl[2], bl[3]);
            }
        }
        #pragma unroll
        for (int j8 = 0; j8 < 32; j8++) {
            int cb = p * 256 + 8 * j8 + ec;
            *(float2*)(g_P + (size_t)(m0 + r0) * 512 + cb)     = make_float2(acc[4*j8+0], acc[4*j8+1]);
            *(float2*)(g_P + (size_t)(m0 + r0 + 8) * 512 + cb) = make_float2(acc[4*j8+2], acc[4*j8+3]);
        }
    }
}

// ---------------------------------------------------------------------------
// Edge kernel, occupancy-2 layout: 128 threads, 64 edges/CTA, SMEM 105472 B.
//  A1H @0 (9216), A1L @9216 (9216), B1 @18432 (18432, staged 4x),
//  Psum @36864 (64x260 f32 = 66560) -> 103424, misc @103424 (2048) -> 105472
//  W2 reload: part1 (36864) @0 after GEMM1; part2 (32768) @36864 after epi1.
// ---------------------------------------------------------------------------
#define OFF_A1H  0
#define OFF_A1L  9216
#define OFF_B1   18432
#define OFF_PS   36864
#define OFF_MISC 103424
#define EDGE_SMEM 105472
#define PSTR 260

__global__ __launch_bounds__(128, 2) void edge_kernel(
    const float* __restrict__ ef,
    const int* __restrict__ rawsrc, const int* __restrict__ rawdst,
    const float* __restrict__ be1, const float* __restrict__ ba1,
    const float* __restrict__ be2, const float* __restrict__ ba2,
    float* __restrict__ ef_out)
{
    extern __shared__ char smc[];
    const uint32_t smb = smem_u32(smc);
    const int tid = threadIdx.x, wid = tid >> 5, lane = tid & 31;
    const int e0 = blockIdx.x * 64;

    int*   sSrc  = (int*)(smc + OFF_MISC);
    int*   sDst  = (int*)(smc + OFF_MISC + 256);
    float* sBias = (float*)(smc + OFF_MISC + 512);
    float* sB2b  = (float*)(smc + OFF_MISC + 1536);
    float* sPs   = (float*)(smc + OFF_PS);

    // B1 stage 0 (Wh, n 0..127)
    #pragma unroll
    for (int i = 0; i < 9; i++)
        cpa16(smb + OFF_B1 + (tid + 128 * i) * 16, (const char*)g_B1e + (tid + 128 * i) * 16);
    CP_COMMIT();

    const int is64 = g_idx64;
    if (tid < 64) sSrc[tid] = is64 ? rawsrc[2 * (e0 + tid)] : rawsrc[e0 + tid];
    else { int m = tid - 64; sDst[m] = is64 ? rawdst[2 * (e0 + m)] : rawdst[e0 + m]; }
    if (tid < 64)
        ((float4*)sBias)[tid] = (tid < 32) ? ((const float4*)be1)[tid] : ((const float4*)ba1)[tid - 32];
    else if (tid < 96)
        ((float4*)sB2b)[tid - 64] = (tid < 80) ? ((const float4*)be2)[tid - 64] : ((const float4*)ba2)[tid - 80];

    // gather ef rows, split hi/lo
    {
        const int m = tid >> 1, h = tid & 1;
        const float* row = ef + (size_t)(e0 + m) * 64;
        #pragma unroll
        for (int it = 0; it < 8; it++) {
            int q = h * 8 + it;
            float4 v = ((const float4*)row)[q];
            uint32_t h0 = packh2(v.x, v.y), h1 = packh2(v.z, v.w);
            float2 f0 = unpackh2(h0), f1 = unpackh2(h1);
            uint32_t l0 = packh2(v.x - f0.x, v.y - f0.y), l1 = packh2(v.z - f1.x, v.w - f1.y);
            *(uint2*)(smc + OFF_A1H + m * 144 + q * 8) = make_uint2(h0, h1);
            *(uint2*)(smc + OFF_A1L + m * 144 + q * 8) = make_uint2(l0, l1);
        }
    }

    const int wr = wid * 16;
    const uint32_t aH = smb + OFF_A1H + (uint32_t)((wr + (lane & 15)) * 144 + ((lane >> 4) * 8) * 2);
    const uint32_t aL = aH + 9216;
    const uint32_t bln = (uint32_t)((((lane >> 4) << 3) + (lane & 7)) * 144 + (((lane >> 3) & 1) ? 16 : 0));
    const uint32_t bB = smb + OFF_B1 + bln;

    float acc[128];
    #pragma unroll
    for (int i = 0; i < 128; i++) acc[i] = 0.f;

    // ---- GEMM1 in 4 B-stages: {Wh n0, Wh n1, Wl n0, Wl n1}; P gather interleaved
    #pragma unroll
    for (int s = 0; s < 4; s++) {
        CP_WAIT0();
        __syncthreads();
        // P gather: 4 edges per warp per stage
        #pragma unroll
        for (int t = 0; t < 4; t++) {
            int m = (wid << 4) + s * 4 + t;
            const float4* ps = (const float4*)(g_P + (size_t)sSrc[m] * 512);
            const float4* pd = (const float4*)(g_P + (size_t)sDst[m] * 512 + 256);
            #pragma unroll
            for (int j = 0; j < 2; j++) {
                int f4 = lane + 32 * j;
                float4 a = ps[f4], b = pd[f4];
                *(float4*)(sPs + m * PSTR + f4 * 4) =
                    make_float4(a.x + b.x, a.y + b.y, a.z + b.z, a.w + b.w);
            }
        }
        const int jbase = (s & 1) * 8;
        const bool p1 = (s < 2);
        #pragma unroll
        for (int ks = 0; ks < 4; ks++) {
            uint32_t ah[4], al[4];
            ldsm4(ah, aH + ks * 32);
            if (p1) ldsm4(al, aL + ks * 32);
            #pragma unroll
            for (int j2l = 0; j2l < 8; j2l++) {
                uint32_t bh[4];
                ldsm4(bh, bB + j2l * 2304 + ks * 32);
                int j2 = jbase + j2l;
                mma16816(&acc[(2*j2+0)*4], ah, bh[0], bh[1]);
                mma16816(&acc[(2*j2+1)*4], ah, bh[2], bh[3]);
                if (p1) {
                    mma16816(&acc[(2*j2+0)*4], al, bh[0], bh[1]);
                    mma16816(&acc[(2*j2+1)*4], al, bh[2], bh[3]);
                }
            }
        }
        __syncthreads();
        if (s < 3) {
            #pragma unroll
            for (int i = 0; i < 9; i++)
                cpa16(smb + OFF_B1 + (tid + 128 * i) * 16,
                      (const char*)g_B1e + (s + 1) * 18432 + (tid + 128 * i) * 16);
            CP_COMMIT();
        }
    }

    // W2 part1 (36864 B @0) — A1/B1 regions dead
    #pragma unroll
    for (int i = 0; i < 18; i++)
        cpa16(smb + (tid + 128 * i) * 16, (const char*)g_W2 + (tid + 128 * i) * 16);
    CP_COMMIT();

    // ---- epilogue 1: H = relu(acc + Psum + bias) -> hi/lo h2 regs ----
    uint32_t hH[64], hL[64];
    {
        const int r0 = wr + (lane >> 2);
        const int ec = 2 * (lane & 3);
        #pragma unroll
        for (int j8 = 0; j8 < 32; j8++) {
            int cb = 8 * j8 + ec;
            float2 p0 = *(float2*)(sPs + r0 * PSTR + cb);
            float2 p1v = *(float2*)(sPs + (r0 + 8) * PSTR + cb);
            float b0 = sBias[cb], b1 = sBias[cb + 1];
            float v0 = fmaxf(acc[4*j8+0] + p0.x + b0, 0.f);
            float v1 = fmaxf(acc[4*j8+1] + p0.y + b1, 0.f);
            float v2 = fmaxf(acc[4*j8+2] + p1v.x + b0, 0.f);
            float v3 = fmaxf(acc[4*j8+3] + p1v.y + b1, 0.f);
            uint32_t h01 = packh2(v0, v1);
            float2 f01 = unpackh2(h01);
            uint32_t l01 = packh2(v0 - f01.x, v1 - f01.y);
            uint32_t h23 = packh2(v2, v3);
            float2 f23 = unpackh2(h23);
            uint32_t l23 = packh2(v2 - f23.x, v3 - f23.y);
            hH[2*j8]   = h01; hL[2*j8]   = l01;
            hH[2*j8+1] = h23; hL[2*j8+1] = l23;
        }
    }
    __syncthreads();   // Psum reads done before part2 overwrites its head

    // W2 part2 (32768 B @36864)
    #pragma unroll
    for (int i = 0; i < 16; i++)
        cpa16(smb + 36864 + (tid + 128 * i) * 16, (const char*)g_W2 + 36864 + (tid + 128 * i) * 16);
    CP_COMMIT();
    CP_WAIT1();        // part1 complete; part2 may still be in flight
    __syncthreads();

    // ---- GEMM2: hf=0 (gate e, W2 part1), then wait part2, hf=1 (gate a) ----
    const uint32_t w2ln = (uint32_t)((((lane >> 4) << 3) + (lane & 7)) * 272 + (((lane >> 3) & 1) ? 16 : 0));
    float acc2[64];
    #pragma unroll
    for (int i = 0; i < 64; i++) acc2[i] = 0.f;

    #pragma unroll
    for (int hf = 0; hf < 2; hf++) {
        if (hf == 1) { CP_WAIT0(); __syncthreads(); }
        const uint32_t wb = smb + (uint32_t)(hf * 34816) + w2ln;
        #pragma unroll
        for (int kc = 0; kc < 8; kc++) {
            int jb = 2 * (hf * 16 + 2 * kc);
            uint32_t ah[4] = { hH[jb], hH[jb+1], hH[jb+2], hH[jb+3] };
            uint32_t al[4] = { hL[jb], hL[jb+1], hL[jb+2], hL[jb+3] };
            #pragma unroll
            for (int j2 = 0; j2 < 4; j2++) {
                uint32_t bh[4], bl[4];
                ldsm4(bh, wb + j2 * 4352 + kc * 32);
                ldsm4(bl, wb + 17408 + j2 * 4352 + kc * 32);
                float* c0 = &acc2[hf * 32 + (2*j2+0) * 4];
                float* c1 = &acc2[hf * 32 + (2*j2+1) * 4];
                mma16816(c0, ah, bh[0], bh[1]); mma16816(c1, ah, bh[2], bh[3]);
                mma16816(c0, al, bh[0], bh[1]); mma16816(c1, al, bh[2], bh[3]);
                mma16816(c0, ah, bl[0], bl[1]); mma16816(c1, ah, bl[2], bl[3]);
            }
        }
    }

    // ---- epilogue 2 ----
    {
        const int r0 = wr + (lane >> 2), r1 = r0 + 8;
        const int ec = 2 * (lane & 3);
        const int d0 = sDst[r0], d1 = sDst[r1];
        float* eo0 = ef_out + (size_t)(e0 + r0) * 64;
        float* eo1 = ef_out + (size_t)(e0 + r1) * 64;
        float* ag0 = g_agg + (size_t)d0 * 64;
        float* ag1 = g_agg + (size_t)d1 * 64;
        #pragma unroll
        for (int j8 = 0; j8 < 8; j8++) {
            int cb = j8 * 8 + ec;
            float be0 = sB2b[cb], be1v = sB2b[cb + 1];
            float ba0 = sB2b[64 + cb], ba1v = sB2b[64 + cb + 1];
            float ex0 = acc2[j8*4+0] + be0, ex1 = acc2[j8*4+1] + be1v;
            float ax0 = acc2[32 + j8*4+0] + ba0, ax1 = acc2[32 + j8*4+1] + ba1v;
            float m0 = ex0 / (1.f + __expf(-ax0));
            float m1 = ex1 / (1.f + __expf(-ax1));
            *(float2*)(eo0 + cb) = make_float2(m0, m1);
            red2(ag0 + cb, m0, m1);
            float ey0 = acc2[j8*4+2] + be0, ey1 = acc2[j8*4+3] + be1v;
            float ay0 = acc2[32 + j8*4+2] + ba0, ay1 = acc2[32 + j8*4+3] + ba1v;
            float n0 = ey0 / (1.f + __expf(-ay0));
            float n1 = ey1 / (1.f + __expf(-ay1));
            *(float2*)(eo1 + cb) = make_float2(n0, n1);
            red2(ag1 + cb, n0, n1);
        }
    }
}

// ---------------------------------------------------------------------------
// Node kernel (HMMA, f32-acc 3-term — R6 version)
// ---------------------------------------------------------------------------
#define NOFF_B1  69632
#define NOFF_W2  139264
#define NOFF_MSC 174080
#define NODE_SMEM 174848

__global__ __launch_bounds__(256, 1) void node_kernel(
    const float* __restrict__ nf,
    const float* __restrict__ bn1, const float* __restrict__ bn2,
    float* __restrict__ nf_out)
{
    extern __shared__ char smc[];
    const uint32_t smb = smem_u32(smc);
    const int tid = threadIdx.x, wid = tid >> 5, lane = tid & 31;
    const int m0 = blockIdx.x * 128;
    float* sB1b = (float*)(smc + NOFF_MSC);
    float* sB2b = (float*)(smc + NOFF_MSC + 512);

    #pragma unroll
    for (int i = 0; i < 17; i++)
        cpa16(smb + NOFF_B1 + (tid + 256 * i) * 16, (const char*)g_Wn1 + (tid + 256 * i) * 16);
    #pragma unroll
    for (int i = 0; i < 9; i++) {
        int idx = tid + 256 * i;
        if (idx < 2176) cpa16(smb + NOFF_W2 + idx * 16, (const char*)g_Wn2 + idx * 16);
    }
    CP_COMMIT();

    if (tid < 32) ((float4*)sB1b)[tid] = ((const float4*)bn1)[tid];
    else if (tid < 48) ((float4*)sB2b)[tid - 32] = ((const float4*)bn2)[tid - 32];

    {
        const int m = tid >> 1, h = tid & 1;
        const int node = m0 + m;
        const float4* src = (h == 0) ? (const float4*)(g_agg + (size_t)node * 64)
                                     : (const float4*)(nf + (size_t)node * 64);
        #pragma unroll
        for (int it = 0; it < 16; it++) {
            float4 v = (node < NN) ? src[it] : make_float4(0.f, 0.f, 0.f, 0.f);
            int k = h * 64 + it * 4;
            uint32_t h0 = packh2(v.x, v.y), h1 = packh2(v.z, v.w);
            float2 f0 = unpackh2(h0), f1 = unpackh2(h1);
            uint32_t l0 = packh2(v.x - f0.x, v.y - f0.y), l1 = packh2(v.z - f1.x, v.w - f1.y);
            *(uint2*)(smc + 0     + m * 272 + k * 2) = make_uint2(h0, h1);
            *(uint2*)(smc + 34816 + m * 272 + k * 2) = make_uint2(l0, l1);
        }
    }
    CP_WAIT0();
    __syncthreads();

    const int wr = wid * 16;
    const uint32_t aH = smb + (uint32_t)((wr + (lane & 15)) * 272 + ((lane >> 4) * 8) * 2);
    const uint32_t aL = aH + 34816;
    const uint32_t bln = (uint32_t)((((lane >> 4) << 3) + (lane & 7)) * 272 + (((lane >> 3) & 1) ? 16 : 0));

    float acc[64];
    #pragma unroll
    for (int i = 0; i < 64; i++) acc[i] = 0.f;
    {
        const uint32_t bH = smb + NOFF_B1 + bln;
        const uint32_t bL = bH + 34816;
        #pragma unroll
        for (int ks = 0; ks < 8; ks++) {
            uint32_t ah[4], al[4];
            ldsm4(ah, aH + ks * 32);
            ldsm4(al, aL + ks * 32);
            #pragma unroll
            for (int j2 = 0; j2 < 8; j2++) {
                uint32_t bh[4], bl[4];
                ldsm4(bh, bH + j2 * 4352 + ks * 32);
                ldsm4(bl, bL + j2 * 4352 + ks * 32);
                float* c0 = &acc[(2*j2+0)*4];
                float* c1 = &acc[(2*j2+1)*4];
                mma16816(c0, ah, bh[0], bh[1]); mma16816(c1, ah, bh[2], bh[3]);
                mma16816(c0, al, bh[0], bh[1]); mma16816(c1, al, bh[2], bh[3]);
                mma16816(c0, ah, bl[0], bl[1]); mma16816(c1, ah, bl[2], bl[3]);
            }
        }
    }

    uint32_t hH[32], hL[32];
    {
        const int ec = 2 * (lane & 3);
        #pragma unroll
        for (int j8 = 0; j8 < 16; j8++) {
            int cb = 8 * j8 + ec;
            float b0 = sB1b[cb], b1 = sB1b[cb + 1];
            float v0 = fmaxf(acc[4*j8+0] + b0, 0.f);
            float v1 = fmaxf(acc[4*j8+1] + b1, 0.f);
            float v2 = fmaxf(acc[4*j8+2] + b0, 0.f);
            float v3 = fmaxf(acc[4*j8+3] + b1, 0.f);
            uint32_t h01 = packh2(v0, v1);
            float2 f01 = unpackh2(h01);
            uint32_t l01 = packh2(v0 - f01.x, v1 - f01.y);
            uint32_t h23 = packh2(v2, v3);
            float2 f23 = unpackh2(h23);
            uint32_t l23 = packh2(v2 - f23.x, v3 - f23.y);
            hH[2*j8] = h01; hL[2*j8] = l01;
            hH[2*j8+1] = h23; hL[2*j8+1] = l23;
        }
    }

    float acc2[32];
    #pragma unroll
    for (int i = 0; i < 32; i++) acc2[i] = 0.f;
    {
        const uint32_t wb = smb + NOFF_W2 + bln;
        #pragma unroll
        for (int kc = 0; kc < 8; kc++) {
            uint32_t ah[4] = { hH[4*kc], hH[4*kc+1], hH[4*kc+2], hH[4*kc+3] };
            uint32_t al[4] = { hL[4*kc], hL[4*kc+1], hL[4*kc+2], hL[4*kc+3] };
            #pragma unroll
            for (int j2 = 0; j2 < 4; j2++) {
                uint32_t bh[4], bl[4];
                ldsm4(bh, wb + j2 * 4352 + kc * 32);
                ldsm4(bl, wb + 17408 + j2 * 4352 + kc * 32);
                float* c0 = &acc2[(2*j2+0)*4];
                float* c1 = &acc2[(2*j2+1)*4];
                mma16816(c0, ah, bh[0], bh[1]); mma16816(c1, ah, bh[2], bh[3]);
                mma16816(c0, al, bh[0], bh[1]); mma16816(c1, al, bh[2], bh[3]);
                mma16816(c0, ah, bl[0], bl[1]); mma16816(c1, ah, bl[2], bl[3]);
            }
        }
    }

    {
        const int r0 = wr + (lane >> 2);
        const int ec = 2 * (lane & 3);
        const int n0 = m0 + r0, n1 = n0 + 8;
        #pragma unroll
        for (int j8 = 0; j8 < 8; j8++) {
            int cb = 8 * j8 + ec;
            float b0 = sB2b[cb], b1 = sB2b[cb + 1];
            if (n0 < NN)
                *(float2*)(nf_out + (size_t)n0 * 64 + cb) =
                    make_float2(acc2[4*j8+0] + b0, acc2[4*j8+1] + b1);
            if (n1 < NN)
                *(float2*)(nf_out + (size_t)n1 * 64 + cb) =
                    make_float2(acc2[4*j8+2] + b0, acc2[4*j8+3] + b1);
        }
    }
}

// ---------------------------------------------------------------------------
extern "C" void kernel_launch(void* const* d_in, const int* in_sizes, int n_in,
                              void* d_out, int out_size)
{
    const float* nf  = (const float*)d_in[0];
    const float* ef  = (const float*)d_in[1];
    const float* We1 = (const float*)d_in[4];
    const float* be1 = (const float*)d_in[5];
    const float* We2 = (const float*)d_in[6];
    const float* be2 = (const float*)d_in[7];
    const float* Wa1 = (const float*)d_in[8];
    const float* ba1 = (const float*)d_in[9];
    const float* Wa2 = (const float*)d_in[10];
    const float* ba2 = (const float*)d_in[11];
    const float* Wn1 = (const float*)d_in[12];
    const float* bn1 = (const float*)d_in[13];
    const float* Wn2 = (const float*)d_in[14];
    const float* bn2 = (const float*)d_in[15];

    float* nf_out = (float*)d_out;
    float* ef_out = nf_out + (size_t)NN * 64;

    cudaFuncSetAttribute(prep_P_kernel, cudaFuncAttributeMaxDynamicSharedMemorySize, PREP_SMEM);
    cudaFuncSetAttribute(edge_kernel, cudaFuncAttributeMaxDynamicSharedMemorySize, EDGE_SMEM);
    cudaFuncSetAttribute(node_kernel, cudaFuncAttributeMaxDynamicSharedMemorySize, NODE_SMEM);

    zp_kernel<<<3126, 256>>>((const unsigned int*)d_in[2]);
    prepA_kernel<<<256, 256>>>(We1, Wa1, We2, Wa2);
    prepB_kernel<<<256, 256>>>(We1, Wa1);
    prepC_kernel<<<192, 256>>>(Wn1, Wn2);
    prep_P_kernel<<<391, 256, PREP_SMEM>>>(nf);
    edge_kernel<<<E_EDGES / 64, 128, EDGE_SMEM>>>(
        ef, (const int*)d_in[2], (const int*)d_in[3],
        be1, ba1, be2, ba2, ef_out);
    node_kernel<<<391, 256, NODE_SMEM>>>(nf, bn1, bn2, nf_out);
}

// round 9
// speedup vs baseline: 1.2991x; 1.2299x over previous
#include <cuda_runtime.h>
#include <cuda_fp16.h>
#include <math.h>
#include <stdint.h>

#define E_EDGES 800000
#define NN      50000
typedef unsigned long long ull;

__device__ int    g_idx64;
__device__ float  g_agg[(size_t)NN * 64];
__device__ float  g_P[(size_t)50048 * 512];   // [node][ P_src(256) | P_dst(256) ]
__device__ __half g_B1e[2 * 256 * 72];        // ef-part W1: [hi|lo][256 n][72 kpad]
__device__ __half g_BP[2 * 512 * 72];         // P-prep W1:  [hi|lo][512 n][72 kpad]
__device__ __half g_W2[2 * 2 * 64 * 136];     // [gate][hi|lo][64 n][136 kpad]
__device__ __half g_Wn1[2 * 128 * 136];       // node W1: [hi|lo][128 n][136 kpad]
__device__ __half g_Wn2[2 * 64 * 136];        // node W2: [hi|lo][64 n][136 kpad]

// ---------------- helpers ----------------------------------------------------
__device__ __forceinline__ uint32_t smem_u32(const void* p) {
    uint32_t a;
    asm("{ .reg .u64 t; cvta.to.shared.u64 t, %1; cvt.u32.u64 %0, t; }" : "=r"(a) : "l"(p));
    return a;
}
__device__ __forceinline__ void ldsm4(uint32_t* r, uint32_t addr) {
    asm volatile("ldmatrix.sync.aligned.m8n8.x4.shared.b16 {%0,%1,%2,%3}, [%4];"
                 : "=r"(r[0]), "=r"(r[1]), "=r"(r[2]), "=r"(r[3]) : "r"(addr));
}
__device__ __forceinline__ void mma16816(float* c, const uint32_t* a, uint32_t b0, uint32_t b1) {
    asm volatile("mma.sync.aligned.m16n8k16.row.col.f32.f16.f16.f32 "
                 "{%0,%1,%2,%3}, {%4,%5,%6,%7}, {%8,%9}, {%0,%1,%2,%3};"
                 : "+f"(c[0]), "+f"(c[1]), "+f"(c[2]), "+f"(c[3])
                 : "r"(a[0]), "r"(a[1]), "r"(a[2]), "r"(a[3]), "r"(b0), "r"(b1));
}
__device__ __forceinline__ void cpa16(uint32_t dst, const void* src) {
    asm volatile("cp.async.cg.shared.global [%0], [%1], 16;" :: "r"(dst), "l"(src));
}
#define CP_COMMIT() asm volatile("cp.async.commit_group;" ::: "memory")
#define CP_WAIT0()  asm volatile("cp.async.wait_group 0;" ::: "memory")
#define CP_WAIT1()  asm volatile("cp.async.wait_group 1;" ::: "memory")
__device__ __forceinline__ void red2(float* p, float x, float y) {
    asm volatile("red.global.add.v2.f32 [%0], {%1,%2};" :: "l"(p), "f"(x), "f"(y) : "memory");
}
__device__ __forceinline__ uint32_t packh2(float x, float y) {
    __half2 h = __floats2half2_rn(x, y);
    return *(uint32_t*)&h;
}
__device__ __forceinline__ float2 unpackh2(uint32_t u) {
    return __half22float2(*(__half2*)&u);
}

// ---------------------------------------------------------------------------
__global__ void zp_kernel(const unsigned int* __restrict__ raw) {
    if (blockIdx.x < 3125) {
        int i = blockIdx.x * 256 + threadIdx.x;
        ((float4*)g_agg)[i] = make_float4(0.f, 0.f, 0.f, 0.f);
    } else {
        __shared__ int any;
        if (threadIdx.x == 0) any = 0;
        __syncthreads();
        int f = 0;
        for (int i = threadIdx.x; i < 2048; i += blockDim.x)
            if (raw[2 * i + 1] != 0u) f = 1;
        if (f) atomicExch(&any, 1);
        __syncthreads();
        if (threadIdx.x == 0) g_idx64 = (any == 0) ? 1 : 0;
    }
}
__global__ void prepA_kernel(const float* __restrict__ We1, const float* __restrict__ Wa1,
                             const float* __restrict__ We2, const float* __restrict__ Wa2) {
    if (blockIdx.x < 128) {
        int gi = blockIdx.x * 256 + threadIdx.x;
        int p = gi >> 14, r = gi & 16383;
        int n = r >> 6, kk = r & 63;
        int k = 128 + kk;
        float w = (n < 128) ? We1[k * 128 + n] : Wa1[k * 128 + (n - 128)];
        __half hi = __float2half_rn(w);
        __half v = (p == 0) ? hi : __float2half_rn(w - __half2float(hi));
        g_B1e[(p * 256 + n) * 72 + kk] = v;
    } else {
        int gi = (blockIdx.x - 128) * 256 + threadIdx.x;
        int g = gi >> 14, p = (gi >> 13) & 1;
        int r = gi & 8191, n = r >> 7, k = r & 127;
        const float* W = g ? Wa2 : We2;
        float w = W[k * 64 + n];
        __half hi = __float2half_rn(w);
        __half v = (p == 0) ? hi : __float2half_rn(w - __half2float(hi));
        g_W2[((g * 2 + p) * 64 + n) * 136 + k] = v;
    }
}
__global__ void prepB_kernel(const float* __restrict__ We1, const float* __restrict__ Wa1) {
    int gi = blockIdx.x * 256 + threadIdx.x;
    int p = gi >> 15, r = gi & 32767;
    int nIdx = r >> 6, kk = r & 63;
    int part = nIdx >> 8, c = nIdx & 255;
    int k = part * 64 + kk;
    float w = (c < 128) ? We1[k * 128 + c] : Wa1[k * 128 + (c - 128)];
    __half hi = __float2half_rn(w);
    __half v = (p == 0) ? hi : __float2half_rn(w - __half2float(hi));
    g_BP[(p * 512 + nIdx) * 72 + kk] = v;
}
__global__ void prepC_kernel(const float* __restrict__ Wn1, const float* __restrict__ Wn2) {
    if (blockIdx.x < 128) {
        int gi = blockIdx.x * 256 + threadIdx.x;
        int p = gi >> 14, r = gi & 16383;
        int n = r >> 7, k = r & 127;
        float w = Wn1[k * 128 + n];
        __half hi = __float2half_rn(w);
        __half v = (p == 0) ? hi : __float2half_rn(w - __half2float(hi));
        g_Wn1[(p * 128 + n) * 136 + k] = v;
    } else {
        int gi = (blockIdx.x - 128) * 256 + threadIdx.x;
        int p = gi >> 13, r = gi & 8191;
        int n = r >> 7, k = r & 127;
        float w = Wn2[k * 64 + n];
        __half hi = __float2half_rn(w);
        __half v = (p == 0) ? hi : __float2half_rn(w - __half2float(hi));
        g_Wn2[(p * 64 + n) * 136 + k] = v;
    }
}

// ---------------------------------------------------------------------------
// prep_P: P[n][512] = nf[n] @ [W_src | W_dst], split-fp16 3-term HMMA.
// ---------------------------------------------------------------------------
#define PREP_SMEM 184320
__global__ __launch_bounds__(256, 1) void prep_P_kernel(const float* __restrict__ nf)
{
    extern __shared__ char smc[];
    const uint32_t smb = smem_u32(smc);
    const int tid = threadIdx.x, wid = tid >> 5, lane = tid & 31;
    const int m0 = blockIdx.x * 128;

    #pragma unroll
    for (int i = 0; i < 36; i++)
        cpa16(smb + 36864 + (tid + 256 * i) * 16, (const char*)g_BP + (tid + 256 * i) * 16);
    CP_COMMIT();

    {
        const int m = tid >> 1, h = tid & 1;
        const int node = m0 + m;
        const float* row = nf + (size_t)node * 64;
        #pragma unroll
        for (int it = 0; it < 8; it++) {
            int q = h * 8 + it;
            float4 v = (node < NN) ? ((const float4*)row)[q] : make_float4(0.f, 0.f, 0.f, 0.f);
            uint32_t h0 = packh2(v.x, v.y), h1 = packh2(v.z, v.w);
            float2 f0 = unpackh2(h0), f1 = unpackh2(h1);
            uint32_t l0 = packh2(v.x - f0.x, v.y - f0.y), l1 = packh2(v.z - f1.x, v.w - f1.y);
            *(uint2*)(smc + 0     + m * 144 + q * 8) = make_uint2(h0, h1);
            *(uint2*)(smc + 18432 + m * 144 + q * 8) = make_uint2(l0, l1);
        }
    }
    CP_WAIT0();
    __syncthreads();

    const int wr = wid * 16;
    const uint32_t aH = smb + (uint32_t)((wr + (lane & 15)) * 144 + ((lane >> 4) * 8) * 2);
    const uint32_t aL = aH + 18432;
    const uint32_t bln = (uint32_t)((((lane >> 4) << 3) + (lane & 7)) * 144 + (((lane >> 3) & 1) ? 16 : 0));
    const int r0 = wr + (lane >> 2);
    const int ec = 2 * (lane & 3);

    #pragma unroll
    for (int p = 0; p < 2; p++) {
        float acc[128];
        #pragma unroll
        for (int i = 0; i < 128; i++) acc[i] = 0.f;
        const uint32_t bH = smb + 36864  + (uint32_t)(p * 36864) + bln;
        const uint32_t bL = bH + 73728;
        #pragma unroll
        for (int ks = 0; ks < 4; ks++) {
            uint32_t ah[4], al[4];
            ldsm4(ah, aH + ks * 32);
            ldsm4(al, aL + ks * 32);
            #pragma unroll
            for (int j2 = 0; j2 < 16; j2++) {
                uint32_t bh[4], bl[4];
                ldsm4(bh, bH + j2 * 2304 + ks * 32);
                ldsm4(bl, bL + j2 * 2304 + ks * 32);
                mma16816(&acc[(2*j2+0)*4], ah, bh[0], bh[1]); mma16816(&acc[(2*j2+1)*4], ah, bh[2], bh[3]);
                mma16816(&acc[(2*j2+0)*4], al, bh[0], bh[1]); mma16816(&acc[(2*j2+1)*4], al, bh[2], bh[3]);
                mma16816(&acc[(2*j2+0)*4], ah, bl[0], bl[1]); mma16816(&acc[(2*j2+1)*4], ah, bl[2], bl[3]);
            }
        }
        #pragma unroll
        for (int j8 = 0; j8 < 32; j8++) {
            int cb = p * 256 + 8 * j8 + ec;
            *(float2*)(g_P + (size_t)(m0 + r0) * 512 + cb)     = make_float2(acc[4*j8+0], acc[4*j8+1]);
            *(float2*)(g_P + (size_t)(m0 + r0 + 8) * 512 + cb) = make_float2(acc[4*j8+2], acc[4*j8+3]);
        }
    }
}

// ---------------------------------------------------------------------------
// Edge kernel, occupancy-3 layout: 128 threads, 64 edges/CTA, SMEM 71680 B.
// Phase regions (time-multiplexed):
//   GEMM1:  A1H @0 (9216), A1L @9216 (9216), B1 @18432 (18432, 4 stages)
//   gather: Psum @0 (64 x 260 f32 = 66560)   [A1/B1 dead]
//   GEMM2:  W2 @0 (69632: part1 e-gate 34816, part2 a-gate 34816) [Psum dead]
//   misc @69632 (2048) -> 71680 total ; 3 CTAs x 71680 = 215040 <= 227KB
// ---------------------------------------------------------------------------
#define OFF_A1H  0
#define OFF_A1L  9216
#define OFF_B1   18432
#define OFF_MISC 69632
#define EDGE_SMEM 71680
#define PSTR 260

__global__ __launch_bounds__(128, 3) void edge_kernel(
    const float* __restrict__ ef,
    const int* __restrict__ rawsrc, const int* __restrict__ rawdst,
    const float* __restrict__ be1, const float* __restrict__ ba1,
    const float* __restrict__ be2, const float* __restrict__ ba2,
    float* __restrict__ ef_out)
{
    extern __shared__ char smc[];
    const uint32_t smb = smem_u32(smc);
    const int tid = threadIdx.x, wid = tid >> 5, lane = tid & 31;
    const int e0 = blockIdx.x * 64;

    int*   sSrc  = (int*)(smc + OFF_MISC);
    int*   sDst  = (int*)(smc + OFF_MISC + 256);
    float* sBias = (float*)(smc + OFF_MISC + 512);
    float* sB2b  = (float*)(smc + OFF_MISC + 1536);
    float* sPs   = (float*)(smc);

    // B1 stage 0 (Wh, n 0..127)
    #pragma unroll
    for (int i = 0; i < 9; i++)
        cpa16(smb + OFF_B1 + (tid + 128 * i) * 16, (const char*)g_B1e + (tid + 128 * i) * 16);
    CP_COMMIT();

    const int is64 = g_idx64;
    if (tid < 64) sSrc[tid] = is64 ? rawsrc[2 * (e0 + tid)] : rawsrc[e0 + tid];
    else { int m = tid - 64; sDst[m] = is64 ? rawdst[2 * (e0 + m)] : rawdst[e0 + m]; }
    if (tid < 64)
        ((float4*)sBias)[tid] = (tid < 32) ? ((const float4*)be1)[tid] : ((const float4*)ba1)[tid - 32];
    else if (tid < 96)
        ((float4*)sB2b)[tid - 64] = (tid < 80) ? ((const float4*)be2)[tid - 64] : ((const float4*)ba2)[tid - 80];

    // gather ef rows, split hi/lo
    {
        const int m = tid >> 1, h = tid & 1;
        const float* row = ef + (size_t)(e0 + m) * 64;
        #pragma unroll
        for (int it = 0; it < 8; it++) {
            int q = h * 8 + it;
            float4 v = ((const float4*)row)[q];
            uint32_t h0 = packh2(v.x, v.y), h1 = packh2(v.z, v.w);
            float2 f0 = unpackh2(h0), f1 = unpackh2(h1);
            uint32_t l0 = packh2(v.x - f0.x, v.y - f0.y), l1 = packh2(v.z - f1.x, v.w - f1.y);
            *(uint2*)(smc + OFF_A1H + m * 144 + q * 8) = make_uint2(h0, h1);
            *(uint2*)(smc + OFF_A1L + m * 144 + q * 8) = make_uint2(l0, l1);
        }
    }

    const int wr = wid * 16;
    const uint32_t aH = smb + OFF_A1H + (uint32_t)((wr + (lane & 15)) * 144 + ((lane >> 4) * 8) * 2);
    const uint32_t aL = aH + 9216;
    const uint32_t bln = (uint32_t)((((lane >> 4) << 3) + (lane & 7)) * 144 + (((lane >> 3) & 1) ? 16 : 0));
    const uint32_t bB = smb + OFF_B1 + bln;

    float acc[128];
    #pragma unroll
    for (int i = 0; i < 128; i++) acc[i] = 0.f;

    // ---- GEMM1, 4 B-stages {Wh n0, Wh n1, Wl n0, Wl n1}, single B buffer ----
    #pragma unroll
    for (int s = 0; s < 4; s++) {
        CP_WAIT0();
        __syncthreads();
        const int jbase = (s & 1) * 8;
        const bool p1 = (s < 2);
        #pragma unroll
        for (int ks = 0; ks < 4; ks++) {
            uint32_t ah[4], al[4];
            ldsm4(ah, aH + ks * 32);
            if (p1) ldsm4(al, aL + ks * 32);
            #pragma unroll
            for (int j2l = 0; j2l < 8; j2l++) {
                uint32_t bh[4];
                ldsm4(bh, bB + j2l * 2304 + ks * 32);
                int j2 = jbase + j2l;
                mma16816(&acc[(2*j2+0)*4], ah, bh[0], bh[1]);
                mma16816(&acc[(2*j2+1)*4], ah, bh[2], bh[3]);
                if (p1) {
                    mma16816(&acc[(2*j2+0)*4], al, bh[0], bh[1]);
                    mma16816(&acc[(2*j2+1)*4], al, bh[2], bh[3]);
                }
            }
        }
        __syncthreads();
        if (s < 3) {
            #pragma unroll
            for (int i = 0; i < 9; i++)
                cpa16(smb + OFF_B1 + (tid + 128 * i) * 16,
                      (const char*)g_B1e + (s + 1) * 18432 + (tid + 128 * i) * 16);
            CP_COMMIT();
        }
    }
    // A1/B1 dead. Gather Psum into [0, 66560).

    // ---- P gather: Psum[m][..] = P_src[src[m]] + P_dst[dst[m]][256:] ----
    {
        #pragma unroll
        for (int it = 0; it < 16; it++) {
            int m = (wid << 4) + it;
            const float4* ps = (const float4*)(g_P + (size_t)sSrc[m] * 512);
            const float4* pd = (const float4*)(g_P + (size_t)sDst[m] * 512 + 256);
            #pragma unroll
            for (int j = 0; j < 2; j++) {
                int f4 = lane + 32 * j;
                float4 a = ps[f4], b = pd[f4];
                *(float4*)(sPs + m * PSTR + f4 * 4) =
                    make_float4(a.x + b.x, a.y + b.y, a.z + b.z, a.w + b.w);
            }
        }
    }
    __syncthreads();

    // ---- epilogue 1: H = relu(acc + Psum + bias) -> hi/lo h2 regs ----
    uint32_t hH[64], hL[64];
    {
        const int r0 = wr + (lane >> 2);
        const int ec = 2 * (lane & 3);
        #pragma unroll
        for (int j8 = 0; j8 < 32; j8++) {
            int cb = 8 * j8 + ec;
            float2 p0 = *(float2*)(sPs + r0 * PSTR + cb);
            float2 p1v = *(float2*)(sPs + (r0 + 8) * PSTR + cb);
            float b0 = sBias[cb], b1 = sBias[cb + 1];
            float v0 = fmaxf(acc[4*j8+0] + p0.x + b0, 0.f);
            float v1 = fmaxf(acc[4*j8+1] + p0.y + b1, 0.f);
            float v2 = fmaxf(acc[4*j8+2] + p1v.x + b0, 0.f);
            float v3 = fmaxf(acc[4*j8+3] + p1v.y + b1, 0.f);
            uint32_t h01 = packh2(v0, v1);
            float2 f01 = unpackh2(h01);
            uint32_t l01 = packh2(v0 - f01.x, v1 - f01.y);
            uint32_t h23 = packh2(v2, v3);
            float2 f23 = unpackh2(h23);
            uint32_t l23 = packh2(v2 - f23.x, v3 - f23.y);
            hH[2*j8]   = h01; hL[2*j8]   = l01;
            hH[2*j8+1] = h23; hL[2*j8+1] = l23;
        }
    }
    __syncthreads();   // Psum reads done -> region reusable for W2

    // ---- stage W2: part1 (e gate) @0, part2 (a gate) @34816 ----
    #pragma unroll
    for (int i = 0; i < 17; i++)
        cpa16(smb + (tid + 128 * i) * 16, (const char*)g_W2 + (tid + 128 * i) * 16);
    CP_COMMIT();
    #pragma unroll
    for (int i = 0; i < 17; i++)
        cpa16(smb + 34816 + (tid + 128 * i) * 16, (const char*)g_W2 + 34816 + (tid + 128 * i) * 16);
    CP_COMMIT();
    CP_WAIT1();        // part1 ready
    __syncthreads();

    // ---- GEMM2: hf=0 (gate e), then wait part2, hf=1 (gate a) ----
    const uint32_t w2ln = (uint32_t)((((lane >> 4) << 3) + (lane & 7)) * 272 + (((lane >> 3) & 1) ? 16 : 0));
    float acc2[64];
    #pragma unroll
    for (int i = 0; i < 64; i++) acc2[i] = 0.f;

    #pragma unroll
    for (int hf = 0; hf < 2; hf++) {
        if (hf == 1) { CP_WAIT0(); __syncthreads(); }
        const uint32_t wb = smb + (uint32_t)(hf * 34816) + w2ln;
        #pragma unroll
        for (int kc = 0; kc < 8; kc++) {
            int jb = 2 * (hf * 16 + 2 * kc);
            uint32_t ah[4] = { hH[jb], hH[jb+1], hH[jb+2], hH[jb+3] };
            uint32_t al[4] = { hL[jb], hL[jb+1], hL[jb+2], hL[jb+3] };
            #pragma unroll
            for (int j2 = 0; j2 < 4; j2++) {
                uint32_t bh[4], bl[4];
                ldsm4(bh, wb + j2 * 4352 + kc * 32);
                ldsm4(bl, wb + 17408 + j2 * 4352 + kc * 32);
                float* c0 = &acc2[hf * 32 + (2*j2+0) * 4];
                float* c1 = &acc2[hf * 32 + (2*j2+1) * 4];
                mma16816(c0, ah, bh[0], bh[1]); mma16816(c1, ah, bh[2], bh[3]);
                mma16816(c0, al, bh[0], bh[1]); mma16816(c1, al, bh[2], bh[3]);
                mma16816(c0, ah, bl[0], bl[1]); mma16816(c1, ah, bl[2], bl[3]);
            }
        }
    }

    // ---- epilogue 2 ----
    {
        const int r0 = wr + (lane >> 2), r1 = r0 + 8;
        const int ec = 2 * (lane & 3);
        const int d0 = sDst[r0], d1 = sDst[r1];
        float* eo0 = ef_out + (size_t)(e0 + r0) * 64;
        float* eo1 = ef_out + (size_t)(e0 + r1) * 64;
        float* ag0 = g_agg + (size_t)d0 * 64;
        float* ag1 = g_agg + (size_t)d1 * 64;
        #pragma unroll
        for (int j8 = 0; j8 < 8; j8++) {
            int cb = j8 * 8 + ec;
            float be0 = sB2b[cb], be1v = sB2b[cb + 1];
            float ba0 = sB2b[64 + cb], ba1v = sB2b[64 + cb + 1];
            float ex0 = acc2[j8*4+0] + be0, ex1 = acc2[j8*4+1] + be1v;
            float ax0 = acc2[32 + j8*4+0] + ba0, ax1 = acc2[32 + j8*4+1] + ba1v;
            float m0 = ex0 / (1.f + __expf(-ax0));
            float m1 = ex1 / (1.f + __expf(-ax1));
            *(float2*)(eo0 + cb) = make_float2(m0, m1);
            red2(ag0 + cb, m0, m1);
            float ey0 = acc2[j8*4+2] + be0, ey1 = acc2[j8*4+3] + be1v;
            float ay0 = acc2[32 + j8*4+2] + ba0, ay1 = acc2[32 + j8*4+3] + ba1v;
            float n0 = ey0 / (1.f + __expf(-ay0));
            float n1 = ey1 / (1.f + __expf(-ay1));
            *(float2*)(eo1 + cb) = make_float2(n0, n1);
            red2(ag1 + cb, n0, n1);
        }
    }
}

// ---------------------------------------------------------------------------
// Node kernel (HMMA, f32-acc 3-term)
// ---------------------------------------------------------------------------
#define NOFF_B1  69632
#define NOFF_W2  139264
#define NOFF_MSC 174080
#define NODE_SMEM 174848

__global__ __launch_bounds__(256, 1) void node_kernel(
    const float* __restrict__ nf,
    const float* __restrict__ bn1, const float* __restrict__ bn2,
    float* __restrict__ nf_out)
{
    extern __shared__ char smc[];
    const uint32_t smb = smem_u32(smc);
    const int tid = threadIdx.x, wid = tid >> 5, lane = tid & 31;
    const int m0 = blockIdx.x * 128;
    float* sB1b = (float*)(smc + NOFF_MSC);
    float* sB2b = (float*)(smc + NOFF_MSC + 512);

    #pragma unroll
    for (int i = 0; i < 17; i++)
        cpa16(smb + NOFF_B1 + (tid + 256 * i) * 16, (const char*)g_Wn1 + (tid + 256 * i) * 16);
    #pragma unroll
    for (int i = 0; i < 9; i++) {
        int idx = tid + 256 * i;
        if (idx < 2176) cpa16(smb + NOFF_W2 + idx * 16, (const char*)g_Wn2 + idx * 16);
    }
    CP_COMMIT();

    if (tid < 32) ((float4*)sB1b)[tid] = ((const float4*)bn1)[tid];
    else if (tid < 48) ((float4*)sB2b)[tid - 32] = ((const float4*)bn2)[tid - 32];

    {
        const int m = tid >> 1, h = tid & 1;
        const int node = m0 + m;
        const float4* src = (h == 0) ? (const float4*)(g_agg + (size_t)node * 64)
                                     : (const float4*)(nf + (size_t)node * 64);
        #pragma unroll
        for (int it = 0; it < 16; it++) {
            float4 v = (node < NN) ? src[it] : make_float4(0.f, 0.f, 0.f, 0.f);
            int k = h * 64 + it * 4;
            uint32_t h0 = packh2(v.x, v.y), h1 = packh2(v.z, v.w);
            float2 f0 = unpackh2(h0), f1 = unpackh2(h1);
            uint32_t l0 = packh2(v.x - f0.x, v.y - f0.y), l1 = packh2(v.z - f1.x, v.w - f1.y);
            *(uint2*)(smc + 0     + m * 272 + k * 2) = make_uint2(h0, h1);
            *(uint2*)(smc + 34816 + m * 272 + k * 2) = make_uint2(l0, l1);
        }
    }
    CP_WAIT0();
    __syncthreads();

    const int wr = wid * 16;
    const uint32_t aH = smb + (uint32_t)((wr + (lane & 15)) * 272 + ((lane >> 4) * 8) * 2);
    const uint32_t aL = aH + 34816;
    const uint32_t bln = (uint32_t)((((lane >> 4) << 3) + (lane & 7)) * 272 + (((lane >> 3) & 1) ? 16 : 0));

    float acc[64];
    #pragma unroll
    for (int i = 0; i < 64; i++) acc[i] = 0.f;
    {
        const uint32_t bH = smb + NOFF_B1 + bln;
        const uint32_t bL = bH + 34816;
        #pragma unroll
        for (int ks = 0; ks < 8; ks++) {
            uint32_t ah[4], al[4];
            ldsm4(ah, aH + ks * 32);
            ldsm4(al, aL + ks * 32);
            #pragma unroll
            for (int j2 = 0; j2 < 8; j2++) {
                uint32_t bh[4], bl[4];
                ldsm4(bh, bH + j2 * 4352 + ks * 32);
                ldsm4(bl, bL + j2 * 4352 + ks * 32);
                float* c0 = &acc[(2*j2+0)*4];
                float* c1 = &acc[(2*j2+1)*4];
                mma16816(c0, ah, bh[0], bh[1]); mma16816(c1, ah, bh[2], bh[3]);
                mma16816(c0, al, bh[0], bh[1]); mma16816(c1, al, bh[2], bh[3]);
                mma16816(c0, ah, bl[0], bl[1]); mma16816(c1, ah, bl[2], bl[3]);
            }
        }
    }

    uint32_t hH[32], hL[32];
    {
        const int ec = 2 * (lane & 3);
        #pragma unroll
        for (int j8 = 0; j8 < 16; j8++) {
            int cb = 8 * j8 + ec;
            float b0 = sB1b[cb], b1 = sB1b[cb + 1];
            float v0 = fmaxf(acc[4*j8+0] + b0, 0.f);
            float v1 = fmaxf(acc[4*j8+1] + b1, 0.f);
            float v2 = fmaxf(acc[4*j8+2] + b0, 0.f);
            float v3 = fmaxf(acc[4*j8+3] + b1, 0.f);
            uint32_t h01 = packh2(v0, v1);
            float2 f01 = unpackh2(h01);
            uint32_t l01 = packh2(v0 - f01.x, v1 - f01.y);
            uint32_t h23 = packh2(v2, v3);
            float2 f23 = unpackh2(h23);
            uint32_t l23 = packh2(v2 - f23.x, v3 - f23.y);
            hH[2*j8] = h01; hL[2*j8] = l01;
            hH[2*j8+1] = h23; hL[2*j8+1] = l23;
        }
    }

    float acc2[32];
    #pragma unroll
    for (int i = 0; i < 32; i++) acc2[i] = 0.f;
    {
        const uint32_t wb = smb + NOFF_W2 + bln;
        #pragma unroll
        for (int kc = 0; kc < 8; kc++) {
            uint32_t ah[4] = { hH[4*kc], hH[4*kc+1], hH[4*kc+2], hH[4*kc+3] };
            uint32_t al[4] = { hL[4*kc], hL[4*kc+1], hL[4*kc+2], hL[4*kc+3] };
            #pragma unroll
            for (int j2 = 0; j2 < 4; j2++) {
                uint32_t bh[4], bl[4];
                ldsm4(bh, wb + j2 * 4352 + kc * 32);
                ldsm4(bl, wb + 17408 + j2 * 4352 + kc * 32);
                float* c0 = &acc2[(2*j2+0)*4];
                float* c1 = &acc2[(2*j2+1)*4];
                mma16816(c0, ah, bh[0], bh[1]); mma16816(c1, ah, bh[2], bh[3]);
                mma16816(c0, al, bh[0], bh[1]); mma16816(c1, al, bh[2], bh[3]);
                mma16816(c0, ah, bl[0], bl[1]); mma16816(c1, ah, bl[2], bl[3]);
            }
        }
    }

    {
        const int r0 = wr + (lane >> 2);
        const int ec = 2 * (lane & 3);
        const int n0 = m0 + r0, n1 = n0 + 8;
        #pragma unroll
        for (int j8 = 0; j8 < 8; j8++) {
            int cb = 8 * j8 + ec;
            float b0 = sB2b[cb], b1 = sB2b[cb + 1];
            if (n0 < NN)
                *(float2*)(nf_out + (size_t)n0 * 64 + cb) =
                    make_float2(acc2[4*j8+0] + b0, acc2[4*j8+1] + b1);
            if (n1 < NN)
                *(float2*)(nf_out + (size_t)n1 * 64 + cb) =
                    make_float2(acc2[4*j8+2] + b0, acc2[4*j8+3] + b1);
        }
    }
}

// ---------------------------------------------------------------------------
extern "C" void kernel_launch(void* const* d_in, const int* in_sizes, int n_in,
                              void* d_out, int out_size)
{
    const float* nf  = (const float*)d_in[0];
    const float* ef  = (const float*)d_in[1];
    const float* We1 = (const float*)d_in[4];
    const float* be1 = (const float*)d_in[5];
    const float* We2 = (const float*)d_in[6];
    const float* be2 = (const float*)d_in[7];
    const float* Wa1 = (const float*)d_in[8];
    const float* ba1 = (const float*)d_in[9];
    const float* Wa2 = (const float*)d_in[10];
    const float* ba2 = (const float*)d_in[11];
    const float* Wn1 = (const float*)d_in[12];
    const float* bn1 = (const float*)d_in[13];
    const float* Wn2 = (const float*)d_in[14];
    const float* bn2 = (const float*)d_in[15];

    float* nf_out = (float*)d_out;
    float* ef_out = nf_out + (size_t)NN * 64;

    cudaFuncSetAttribute(prep_P_kernel, cudaFuncAttributeMaxDynamicSharedMemorySize, PREP_SMEM);
    cudaFuncSetAttribute(edge_kernel, cudaFuncAttributeMaxDynamicSharedMemorySize, EDGE_SMEM);
    cudaFuncSetAttribute(node_kernel, cudaFuncAttributeMaxDynamicSharedMemorySize, NODE_SMEM);

    zp_kernel<<<3126, 256>>>((const unsigned int*)d_in[2]);
    prepA_kernel<<<256, 256>>>(We1, Wa1, We2, Wa2);
    prepB_kernel<<<256, 256>>>(We1, Wa1);
    prepC_kernel<<<192, 256>>>(Wn1, Wn2);
    prep_P_kernel<<<391, 256, PREP_SMEM>>>(nf);
    edge_kernel<<<E_EDGES / 64, 128, EDGE_SMEM>>>(
        ef, (const int*)d_in[2], (const int*)d_in[3],
        be1, ba1, be2, ba2, ef_out);
    node_kernel<<<391, 256, NODE_SMEM>>>(nf, bn1, bn2, nf_out);
}